// round 4
// baseline (speedup 1.0000x reference)
#include <cuda_runtime.h>

// Problem constants (fixed by setup_inputs: b=8, N=16384, d=128, T=64)
#define BDIM    8
#define NPIX    16384
#define GRID    8192    // 2 pixels per block: n and n + GRID
#define DDIM    128
#define TDIM    64
#define NCAT    21
#define THRESHV 230.0f
#define TSTRIDE 132     // floats per smem row: 33 granules, 33 % 32 == 1 -> conflict-free
#define PSTRIDE 19      // partials row stride: gcd(19,32)=1 -> conflict-free scalar reads

// Output packing: flattened outputs concatenated in return order, float32.
#define OFF_MASK 2752512u                      // 8*16384*21
#define OFF_NCM  (OFF_MASK + 131072u)
#define OFF_MIND (OFF_NCM  + 131072u)
#define OFF_NC   (OFF_MIND + 131072u)

#define FMA2(acc, x, t) asm("fma.rn.f32x2 %0, %1, %2, %0;" : "+l"(acc) : "l"(x), "l"(t))

static __device__ __forceinline__ void upk2(unsigned long long v, float& a, float& b) {
    asm("mov.b64 {%0,%1}, %2;" : "=f"(a), "=f"(b) : "l"(v));
}
static __device__ __forceinline__ void cpasync16(void* smem_dst, const void* gsrc) {
    unsigned d = (unsigned)__cvta_generic_to_shared(smem_dst);
    asm volatile("cp.async.cg.shared.global [%0], [%1], 16;\n" :: "r"(d), "l"(gsrc));
}

__global__ __launch_bounds__(256, 2) void nnos_kernel(
    const float* __restrict__ frame,   // [8, 16384, 128] f32
    const float* __restrict__ tmpl,    // [64, 16384, 128] f32
    const int*   __restrict__ tclass,  // [64] int32
    float*       __restrict__ out)
{
    __shared__ __align__(16) float t_s[2][TDIM * TSTRIDE];   // 67584 B
    __shared__ __align__(16) float x_s[2][BDIM * TSTRIDE];   //  8448 B
    __shared__ float part[TDIM * PSTRIDE];                    //  4864 B
    __shared__ float x2_s[2][BDIM];

    const int tid  = threadIdx.x;
    const int w    = tid >> 5;
    const int lane = tid & 31;

    // ---- Issue BOTH pixels' loads up front (two cp.async groups) ----
    #pragma unroll
    for (int p = 0; p < 2; ++p) {
        const int n = blockIdx.x + p * GRID;
        const size_t pixbase = (size_t)n * DDIM + 4 * lane;
        #pragma unroll
        for (int i = 0; i < 8; ++i) {
            const int r = i * 8 + w;
            cpasync16(t_s[p] + r * TSTRIDE + 4 * lane,
                      tmpl + (size_t)r * (NPIX * DDIM) + pixbase);
        }
        cpasync16(x_s[p] + w * TSTRIDE + 4 * lane,
                  frame + (size_t)w * (NPIX * DDIM) + pixbase);
        asm volatile("cp.async.commit_group;\n");
    }

    #pragma unroll
    for (int p = 0; p < 2; ++p) {
        if (p == 0) asm volatile("cp.async.wait_group 1;\n");
        else        asm volatile("cp.async.wait_group 0;\n");
        __syncthreads();   // buffer p visible to all; also fences part[] reuse

        const int n = blockIdx.x + p * GRID;

        // ---- x2 for row w from smem (1 LDS.128 per lane + butterfly) ----
        {
            float4 v = *(const float4*)(x_s[p] + w * TSTRIDE + 4 * lane);
            float sq = v.x * v.x + v.y * v.y + v.z * v.z + v.w * v.w;
            #pragma unroll
            for (int off = 16; off; off >>= 1)
                sq += __shfl_xor_sync(0xffffffffu, sq, off);
            if (lane == 0) x2_s[p][w] = sq;
        }

        // ---- Phase 2: warp w -> (t-group c = w&3, k-half kh = w>>2).
        //      lane -> t = 16c + (lane&15), batches b = 4*(lane>>4) + {0..3}.
        {
            const int c  = w & 3;
            const int kh = w >> 2;
            const int tt = lane & 15;
            const int t  = c * 16 + tt;
            const int bh = lane >> 4;

            const float* trow = t_s[p] + t * TSTRIDE + kh * 64;
            const float* xrow = x_s[p] + (4 * bh) * TSTRIDE + kh * 64;

            unsigned long long a0 = 0, a1 = 0, a2 = 0, a3 = 0, t2a = 0;

            #pragma unroll
            for (int g = 0; g < 16; ++g) {
                ulonglong2 tv = *(const ulonglong2*)(trow + g * 4);
                FMA2(t2a, tv.x, tv.x);
                FMA2(t2a, tv.y, tv.y);
                ulonglong2 v0 = *(const ulonglong2*)(xrow + 0 * TSTRIDE + g * 4);
                FMA2(a0, v0.x, tv.x); FMA2(a0, v0.y, tv.y);
                ulonglong2 v1 = *(const ulonglong2*)(xrow + 1 * TSTRIDE + g * 4);
                FMA2(a1, v1.x, tv.x); FMA2(a1, v1.y, tv.y);
                ulonglong2 v2 = *(const ulonglong2*)(xrow + 2 * TSTRIDE + g * 4);
                FMA2(a2, v2.x, tv.x); FMA2(a2, v2.y, tv.y);
                ulonglong2 v3 = *(const ulonglong2*)(xrow + 3 * TSTRIDE + g * 4);
                FMA2(a3, v3.x, tv.x); FMA2(a3, v3.y, tv.y);
            }

            float lo, hi;
            float* pr = part + t * PSTRIDE + 8 * kh + 4 * bh;
            upk2(a0, lo, hi); pr[0] = lo + hi;
            upk2(a1, lo, hi); pr[1] = lo + hi;
            upk2(a2, lo, hi); pr[2] = lo + hi;
            upk2(a3, lo, hi); pr[3] = lo + hi;
            upk2(t2a, lo, hi);
            part[t * PSTRIDE + 16 + kh] = lo + hi;   // both bh lanes write same value
        }
        __syncthreads();

        // ---- Phase 3: warp w owns batch b = w; butterfly argmin; fused epilogue ----
        {
            const int b = w;
            const float* p0 = part + lane * PSTRIDE;
            const float* p1 = part + (lane + 32) * PSTRIDE;

            float xt0 = p0[b] + p0[8 + b];
            float d   = fmaf(-2.0f, xt0, p0[16] + p0[17]);
            int   idx = lane;
            float xt1 = p1[b] + p1[8 + b];
            float d1  = fmaf(-2.0f, xt1, p1[16] + p1[17]);
            if (d1 < d) { d = d1; idx = lane + 32; }      // tie -> lower idx kept

            #pragma unroll
            for (int off = 16; off; off >>= 1) {
                float od = __shfl_xor_sync(0xffffffffu, d, off);
                int   oi = __shfl_xor_sync(0xffffffffu, idx, off);
                if (od < d || (od == d && oi < idx)) { d = od; idx = oi; }
            }
            const int   cls = tclass[idx];
            const float fd  = x2_s[p][b] + d;
            const int   msk = (fd <= THRESHV) ? 1 : 0;
            const size_t bn = (size_t)b * NPIX + n;

            if (lane == 0) {
                out[OFF_MASK + bn] = (float)msk;
                out[OFF_NCM  + bn] = (float)(msk ? cls : (NCAT - 1));
                out[OFF_MIND + bn] = fd;
                out[OFF_NC   + bn] = (float)cls;
            }
            if (lane < NCAT)
                out[bn * NCAT + lane] = (msk && (lane == cls)) ? 1.0f : 0.0f;
        }
        // next iteration's leading __syncthreads orders part[] reuse
    }
}

extern "C" void kernel_launch(void* const* d_in, const int* in_sizes, int n_in,
                              void* d_out, int out_size) {
    const float* frame = (const float*)d_in[0];
    const float* tmpl  = (const float*)d_in[1];
    const int*   cls   = (const int*)d_in[2];
    float*       out   = (float*)d_out;
    (void)in_sizes; (void)n_in; (void)out_size;
    nnos_kernel<<<GRID, 256>>>(frame, tmpl, cls, out);
}

// round 5
// speedup vs baseline: 1.3357x; 1.3357x over previous
#include <cuda_runtime.h>

// Problem constants (fixed by setup_inputs: b=8, N=16384, d=128, T=64)
#define BDIM    8
#define NPIX    16384
#define DDIM    128
#define TDIM    64
#define NCAT    21
#define THRESHV 230.0f
#define TSTRIDE 132     // tile row stride: 33 granules, 33 % 32 == 1 -> conflict-free LDS.128
#define PSTR    33      // partials row stride (odd -> conflict-free scalar reads)

// Output packing: flattened outputs concatenated in return order, float32.
#define OFF_MASK 2752512u                      // 8*16384*21
#define OFF_NCM  (OFF_MASK + 131072u)
#define OFF_MIND (OFF_NCM  + 131072u)
#define OFF_NC   (OFF_MIND + 131072u)

#define FMA2(acc, x, t) asm("fma.rn.f32x2 %0, %1, %2, %0;" : "+l"(acc) : "l"(x), "l"(t))

static __device__ __forceinline__ void upk2(unsigned long long v, float& a, float& b) {
    asm("mov.b64 {%0,%1}, %2;" : "=f"(a), "=f"(b) : "l"(v));
}
static __device__ __forceinline__ void cpasync16(void* smem_dst, const void* gsrc) {
    unsigned d = (unsigned)__cvta_generic_to_shared(smem_dst);
    asm volatile("cp.async.cg.shared.global [%0], [%1], 16;\n" :: "r"(d), "l"(gsrc));
}

__global__ __launch_bounds__(256, 4) void nnos_kernel(
    const float* __restrict__ frame,   // [8, 16384, 128] f32
    const float* __restrict__ tmpl,    // [64, 16384, 128] f32
    const int*   __restrict__ tclass,  // [64] int32
    float*       __restrict__ out)
{
    __shared__ __align__(16) float t_s[TDIM * TSTRIDE];   // 33792 B
    __shared__ __align__(16) float x_s[BDIM * TSTRIDE];   //  4224 B
    __shared__ float part[TDIM * PSTR];                    //  8448 B
    __shared__ float x2_s[BDIM];

    const int n    = blockIdx.x;
    const int tid  = threadIdx.x;
    const int w    = tid >> 5;
    const int lane = tid & 31;

    // ---- Phase 1a: stage templates via cp.async ----
    const size_t pixbase = (size_t)n * DDIM + 4 * lane;
    #pragma unroll
    for (int i = 0; i < 8; ++i) {
        const int r = i * 8 + w;
        cpasync16(t_s + r * TSTRIDE + 4 * lane,
                  tmpl + (size_t)r * (NPIX * DDIM) + pixbase);
    }
    asm volatile("cp.async.commit_group;\n");

    // ---- Phase 1b: frame row w -> smem + x2 reduction (overlaps async copies) ----
    {
        float4 v = *(const float4*)(frame + (size_t)w * (NPIX * DDIM) + pixbase);
        *(float4*)(x_s + w * TSTRIDE + 4 * lane) = v;
        float sq = v.x * v.x + v.y * v.y + v.z * v.z + v.w * v.w;
        #pragma unroll
        for (int off = 16; off; off >>= 1)
            sq += __shfl_xor_sync(0xffffffffu, sq, off);
        if (lane == 0) x2_s[w] = sq;
    }
    asm volatile("cp.async.wait_group 0;\n");
    __syncthreads();

    // ---- Phase 2: warp w -> (t-half tg = w&1 of 32 templates, k-quarter kq = w>>1).
    //      lane -> templates {32tg + tt, 32tg + tt + 16}, batches 4*bh .. 4*bh+3.
    {
        const int tg = w & 1;
        const int kq = w >> 1;
        const int tt = lane & 15;
        const int bh = lane >> 4;
        const int t0 = tg * 32 + tt;
        const int t1 = t0 + 16;
        const int ko = kq * 32;

        const float* tr0 = t_s + t0 * TSTRIDE + ko;
        const float* tr1 = t_s + t1 * TSTRIDE + ko;
        const float* xr  = x_s + (4 * bh) * TSTRIDE + ko;

        unsigned long long a0[4] = {0, 0, 0, 0};
        unsigned long long a1[4] = {0, 0, 0, 0};
        unsigned long long t2a0 = 0, t2a1 = 0;

        #pragma unroll
        for (int g = 0; g < 8; ++g) {
            ulonglong2 tv0 = *(const ulonglong2*)(tr0 + g * 4);
            ulonglong2 tv1 = *(const ulonglong2*)(tr1 + g * 4);
            FMA2(t2a0, tv0.x, tv0.x); FMA2(t2a0, tv0.y, tv0.y);
            FMA2(t2a1, tv1.x, tv1.x); FMA2(t2a1, tv1.y, tv1.y);
            #pragma unroll
            for (int j = 0; j < 4; ++j) {
                ulonglong2 xv = *(const ulonglong2*)(xr + j * TSTRIDE + g * 4);
                FMA2(a0[j], xv.x, tv0.x); FMA2(a0[j], xv.y, tv0.y);
                FMA2(a1[j], xv.x, tv1.x); FMA2(a1[j], xv.y, tv1.y);
            }
        }

        // Fold t2 into partials: part[t][8*kq + b] = t2q - 2*xtq
        float lo, hi;
        upk2(t2a0, lo, hi); const float t20 = lo + hi;
        upk2(t2a1, lo, hi); const float t21 = lo + hi;
        float* pr = part + (8 * kq + 4 * bh);
        #pragma unroll
        for (int j = 0; j < 4; ++j) {
            upk2(a0[j], lo, hi); pr[t0 * PSTR + j] = fmaf(-2.0f, lo + hi, t20);
            upk2(a1[j], lo, hi); pr[t1 * PSTR + j] = fmaf(-2.0f, lo + hi, t21);
        }
    }
    __syncthreads();

    // ---- Phase 3: warp w owns batch b = w; lanes scan t = lane, lane+32;
    //      butterfly argmin; fused epilogue ----
    {
        const int b = w;
        const float* p0 = part + lane * PSTR + b;
        const float* p1 = part + (lane + 32) * PSTR + b;

        float d  = (p0[0] + p0[8]) + (p0[16] + p0[24]);
        float d1 = (p1[0] + p1[8]) + (p1[16] + p1[24]);
        int  idx = lane;
        if (d1 < d) { d = d1; idx = lane + 32; }          // tie -> lower idx kept

        #pragma unroll
        for (int off = 16; off; off >>= 1) {
            float od = __shfl_xor_sync(0xffffffffu, d, off);
            int   oi = __shfl_xor_sync(0xffffffffu, idx, off);
            if (od < d || (od == d && oi < idx)) { d = od; idx = oi; }
        }
        const int   cls = tclass[idx];
        const float fd  = x2_s[b] + d;
        const int   msk = (fd <= THRESHV) ? 1 : 0;
        const size_t bn = (size_t)b * NPIX + n;

        if (lane == 0) {
            out[OFF_MASK + bn] = (float)msk;
            out[OFF_NCM  + bn] = (float)(msk ? cls : (NCAT - 1));
            out[OFF_MIND + bn] = fd;
            out[OFF_NC   + bn] = (float)cls;
        }
        if (lane < NCAT)
            out[bn * NCAT + lane] = (msk && (lane == cls)) ? 1.0f : 0.0f;
    }
}

extern "C" void kernel_launch(void* const* d_in, const int* in_sizes, int n_in,
                              void* d_out, int out_size) {
    const float* frame = (const float*)d_in[0];
    const float* tmpl  = (const float*)d_in[1];
    const int*   cls   = (const int*)d_in[2];
    float*       out   = (float*)d_out;
    (void)in_sizes; (void)n_in; (void)out_size;
    nnos_kernel<<<NPIX, 256>>>(frame, tmpl, cls, out);
}